// round 1
// baseline (speedup 1.0000x reference)
#include <cuda_runtime.h>
#include <math.h>

// Problem constants
#define NBATCH 8
#define CCH    256
#define TSEQ   1024
#define NHEAD  8
#define HDIM   32

// Scratch: K, Q, V in [N, H, T, D] layout; attn out in [N, T, C] layout.
__device__ float g_k[NBATCH * NHEAD * TSEQ * HDIM];
__device__ float g_q[NBATCH * NHEAD * TSEQ * HDIM];
__device__ float g_v[NBATCH * NHEAD * TSEQ * HDIM];
__device__ float g_attn[NBATCH * TSEQ * CCH];

// ---------------------------------------------------------------------------
// Kernel 1: KQV projection.
//   A[m, k] = seq[n, t, c=k] = image[n, k, t]   (m = n*1024 + t)
//   B = w_kqv [256, 768] row-major
//   out o in [0,768): which = o/256 (0=k,1=q,2=v), c = o%256, h = c/32, d = c%32
// Tiled SGEMM: BM=64, BN=64, BK=32, 256 threads, 4x4 register blocking.
// ---------------------------------------------------------------------------
__global__ __launch_bounds__(256) void kqv_gemm(const float* __restrict__ image,
                                                const float* __restrict__ w,
                                                const float* __restrict__ bias) {
    __shared__ float As[32][64];
    __shared__ float Bs[32][64];
    const int bm = blockIdx.y * 64;
    const int bn = blockIdx.x * 64;
    const int tid = threadIdx.x;
    const int tx = tid & 15;       // m direction (fast)
    const int ty = tid >> 4;       // o direction
    const int n  = bm >> 10;       // tile lies within one batch (64 | 1024)
    const int t0 = bm & 1023;

    float acc[4][4] = {};

    for (int k0 = 0; k0 < 256; k0 += 32) {
        #pragma unroll
        for (int l = 0; l < 8; l++) {
            int idx = l * 256 + tid;
            int kk = idx >> 6, mm = idx & 63;
            As[kk][mm] = image[n * 262144 + (k0 + kk) * 1024 + t0 + mm];
        }
        #pragma unroll
        for (int l = 0; l < 8; l++) {
            int idx = l * 256 + tid;
            int kk = idx >> 6, oo = idx & 63;
            Bs[kk][oo] = w[(k0 + kk) * 768 + bn + oo];
        }
        __syncthreads();
        #pragma unroll
        for (int kk = 0; kk < 32; kk++) {
            float ra[4], rb[4];
            #pragma unroll
            for (int i = 0; i < 4; i++) ra[i] = As[kk][tx + 16 * i];
            #pragma unroll
            for (int j = 0; j < 4; j++) rb[j] = Bs[kk][ty * 4 + j];
            #pragma unroll
            for (int i = 0; i < 4; i++)
                #pragma unroll
                for (int j = 0; j < 4; j++)
                    acc[i][j] += ra[i] * rb[j];
        }
        __syncthreads();
    }

    #pragma unroll
    for (int i = 0; i < 4; i++) {
        const int t = t0 + tx + 16 * i;
        #pragma unroll
        for (int j = 0; j < 4; j++) {
            const int o = bn + ty * 4 + j;
            float val = acc[i][j] + bias[o];
            const int which = o >> 8;
            const int c = o & 255;
            const int h = c >> 5;
            const int d = c & 31;
            float* dst = (which == 0) ? g_k : (which == 1) ? g_q : g_v;
            dst[((n * NHEAD + h) * TSEQ + t) * HDIM + d] = val;
        }
    }
}

// ---------------------------------------------------------------------------
// Kernel 2: causal flash attention. One thread = one query row.
// Block: 128 threads (query tile of 128). Grid: (8 q-tiles, 64 n*h).
// K/V tiles of 64 keys staged in shared; online softmax in registers.
// ---------------------------------------------------------------------------
__global__ __launch_bounds__(128) void attn_kernel() {
    const int qt = blockIdx.x;          // 0..7
    const int nh = blockIdx.y;          // 0..63  (n*8 + h)
    const int tid = threadIdx.x;
    const int tq = qt * 128 + tid;      // this thread's query row

    const float* Qb = g_q + (size_t)nh * TSEQ * HDIM;
    const float* Kb = g_k + (size_t)nh * TSEQ * HDIM;
    const float* Vb = g_v + (size_t)nh * TSEQ * HDIM;

    // Query row into registers (8 x float4 = 32 floats)
    float4 q4[8];
    const float4* qsrc = (const float4*)(Qb + (size_t)tq * HDIM);
    #pragma unroll
    for (int d4 = 0; d4 < 8; d4++) q4[d4] = qsrc[d4];

    float acc[32];
    #pragma unroll
    for (int d = 0; d < 32; d++) acc[d] = 0.0f;
    float mmax = -INFINITY;
    float lsum = 0.0f;

    __shared__ float4 Ks[64 * 8];   // 64 keys x 32 dims
    __shared__ float4 Vs[64 * 8];

    const float scale = 0.17677669529663687f;  // 1/sqrt(32)
    const int ntiles = qt * 2 + 2;             // key tiles needed (64-wide)

    for (int kt = 0; kt < ntiles; kt++) {
        __syncthreads();
        const float4* ksrc = (const float4*)(Kb + (size_t)kt * 64 * HDIM);
        const float4* vsrc = (const float4*)(Vb + (size_t)kt * 64 * HDIM);
        #pragma unroll
        for (int l = 0; l < 4; l++) {
            Ks[l * 128 + tid] = ksrc[l * 128 + tid];
            Vs[l * 128 + tid] = vsrc[l * 128 + tid];
        }
        __syncthreads();

        const int base = kt * 64;
        #pragma unroll 4
        for (int j = 0; j < 64; j++) {
            float s = 0.0f;
            #pragma unroll
            for (int d4 = 0; d4 < 8; d4++) {
                float4 k4 = Ks[j * 8 + d4];
                s += q4[d4].x * k4.x + q4[d4].y * k4.y
                   + q4[d4].z * k4.z + q4[d4].w * k4.w;
            }
            s *= scale;
            if (base + j <= tq) {
                if (s <= mmax) {
                    float p = __expf(s - mmax);
                    lsum += p;
                    #pragma unroll
                    for (int d4 = 0; d4 < 8; d4++) {
                        float4 v4 = Vs[j * 8 + d4];
                        acc[d4 * 4 + 0] += p * v4.x;
                        acc[d4 * 4 + 1] += p * v4.y;
                        acc[d4 * 4 + 2] += p * v4.z;
                        acc[d4 * 4 + 3] += p * v4.w;
                    }
                } else {
                    float r = __expf(mmax - s);   // expf(-inf)=0 on first key
                    mmax = s;
                    lsum = lsum * r + 1.0f;
                    #pragma unroll
                    for (int d4 = 0; d4 < 8; d4++) {
                        float4 v4 = Vs[j * 8 + d4];
                        acc[d4 * 4 + 0] = acc[d4 * 4 + 0] * r + v4.x;
                        acc[d4 * 4 + 1] = acc[d4 * 4 + 1] * r + v4.y;
                        acc[d4 * 4 + 2] = acc[d4 * 4 + 2] * r + v4.z;
                        acc[d4 * 4 + 3] = acc[d4 * 4 + 3] * r + v4.w;
                    }
                }
            }
        }
    }

    const float inv = 1.0f / lsum;
    const int n = nh >> 3;
    const int h = nh & 7;
    float4* dst = (float4*)(g_attn + ((size_t)(n * TSEQ + tq)) * CCH + h * HDIM);
    #pragma unroll
    for (int d4 = 0; d4 < 8; d4++) {
        dst[d4] = make_float4(acc[d4 * 4 + 0] * inv, acc[d4 * 4 + 1] * inv,
                              acc[d4 * 4 + 2] * inv, acc[d4 * 4 + 3] * inv);
    }
}

// ---------------------------------------------------------------------------
// Kernel 3: mix projection + bias + residual, stored to [N, C, H, W] output.
//   A[m, k] = g_attn[m*256 + k]  (contiguous rows)
//   B = w_mix [256, 256]
// ---------------------------------------------------------------------------
__global__ __launch_bounds__(256) void mix_gemm(const float* __restrict__ image,
                                                const float* __restrict__ w,
                                                const float* __restrict__ bias,
                                                float* __restrict__ out) {
    __shared__ float As[32][65];   // padded: written kk-major
    __shared__ float Bs[32][64];
    const int bm = blockIdx.y * 64;
    const int bn = blockIdx.x * 64;
    const int tid = threadIdx.x;
    const int tx = tid & 15;
    const int ty = tid >> 4;

    float acc[4][4] = {};

    for (int k0 = 0; k0 < 256; k0 += 32) {
        #pragma unroll
        for (int l = 0; l < 8; l++) {
            int idx = l * 256 + tid;
            int mm = idx >> 5, kk = idx & 31;   // contiguous k per row -> coalesced
            As[kk][mm] = g_attn[(size_t)(bm + mm) * 256 + k0 + kk];
        }
        #pragma unroll
        for (int l = 0; l < 8; l++) {
            int idx = l * 256 + tid;
            int kk = idx >> 6, oo = idx & 63;
            Bs[kk][oo] = w[(k0 + kk) * 256 + bn + oo];
        }
        __syncthreads();
        #pragma unroll
        for (int kk = 0; kk < 32; kk++) {
            float ra[4], rb[4];
            #pragma unroll
            for (int i = 0; i < 4; i++) ra[i] = As[kk][tx + 16 * i];
            #pragma unroll
            for (int j = 0; j < 4; j++) rb[j] = Bs[kk][ty * 4 + j];
            #pragma unroll
            for (int i = 0; i < 4; i++)
                #pragma unroll
                for (int j = 0; j < 4; j++)
                    acc[i][j] += ra[i] * rb[j];
        }
        __syncthreads();
    }

    #pragma unroll
    for (int j = 0; j < 4; j++) {
        const int o = bn + ty * 4 + j;
        const float bo = bias[o];
        #pragma unroll
        for (int i = 0; i < 4; i++) {
            const int m = bm + tx + 16 * i;
            const int n = m >> 10;
            const int t = m & 1023;
            const size_t gidx = (size_t)n * 262144 + (size_t)o * 1024 + t;
            out[gidx] = acc[i][j] + bo + image[gidx];
        }
    }
}

// ---------------------------------------------------------------------------
extern "C" void kernel_launch(void* const* d_in, const int* in_sizes, int n_in,
                              void* d_out, int out_size) {
    const float* image = (const float*)d_in[0];
    const float* w_kqv = (const float*)d_in[1];
    const float* b_kqv = (const float*)d_in[2];
    const float* w_mix = (const float*)d_in[3];
    const float* b_mix = (const float*)d_in[4];
    float* out = (float*)d_out;

    // KQV projection: M=8192, N=768
    dim3 gridA(768 / 64, 8192 / 64);
    kqv_gemm<<<gridA, 256>>>(image, w_kqv, b_kqv);

    // Attention: 8 query tiles x 64 (n,h) pairs
    dim3 gridB(8, 64);
    attn_kernel<<<gridB, 128>>>();

    // Mix + residual: M=8192, N=256
    dim3 gridC(256 / 64, 8192 / 64);
    mix_gemm<<<gridC, 256>>>(image, w_mix, b_mix, out);
}